// round 8
// baseline (speedup 1.0000x reference)
#include <cuda_runtime.h>

#define C     10
#define C2    20
#define HW    128
#define TW    16
#define TH    16
#define PITCH 19            // odd pitch -> conflict-free
#define HALOH 18
#define HS    (PITCH*HALOH) // 342
#define NTHR  256
#define NPP   128           // pixel-pair workers per half

typedef unsigned long long ull;

// shared layout (floats)
#define OFF_F     0
#define OFF_H0    (C*HS)                    // 3420
#define OFF_H1    (2*C*HS)                  // 6840
#define OFF_WREL  (3*C*HS)                  // 10260 (x4B 16B-aligned)
#define OFF_WG2   (OFF_WREL + C*9*C*4)      // 13860
#define OFF_WC2   (OFF_WG2 + C2*C*4)        // 14660
#define OFF_ATTW2 (OFF_WC2 + C*C*4)         // 15060
#define OFF_GB    (OFF_ATTW2 + C2*2)        // 15100
#define OFF_CB    (OFF_GB + C2)             // 15120
#define OFF_B2    (OFF_CB + C)              // 15130
#define OFF_ATTB  (OFF_B2 + C)              // 15140
#define SMEM_FLOATS (OFF_ATTB + 1)
#define SMEM_BYTES (SMEM_FLOATS*4)          // ~60.6 KB -> 3 CTAs/SM

__device__ __forceinline__ float fsigmoid(float x) { return 1.0f / (1.0f + __expf(-x)); }
__device__ __forceinline__ float ftanh_fast(float x) { return 1.0f - 2.0f / (__expf(2.0f * x) + 1.0f); }

__device__ __forceinline__ ull pack2(float lo, float hi) {
    ull r; asm("mov.b64 %0, {%1,%2};" : "=l"(r) : "f"(lo), "f"(hi)); return r;
}
__device__ __forceinline__ void unpack2(ull v, float& lo, float& hi) {
    asm("mov.b64 {%0,%1}, %2;" : "=f"(lo), "=f"(hi) : "l"(v));
}
__device__ __forceinline__ void fma2(ull& acc, ull a, ull b) {
    asm("fma.rn.f32x2 %0, %1, %2, %0;" : "+l"(acc) : "l"(a), "l"(b));
}
__device__ __forceinline__ ull mul2(ull a, ull b) {
    ull r; asm("mul.rn.f32x2 %0, %1, %2;" : "=l"(r) : "l"(a), "l"(b)); return r;
}

__global__ void __launch_bounds__(NTHR, 3)
fused_tree_gru(const float* __restrict__ f_node,
               const float* __restrict__ h0g,
               const float* __restrict__ h1g,
               const float* __restrict__ att_w,
               const float* __restrict__ att_b,
               const float* __restrict__ rel_w,
               const float* __restrict__ bn_gamma,
               const float* __restrict__ bn_beta,
               const float* __restrict__ bn_mean,
               const float* __restrict__ bn_var,
               const float* __restrict__ gates_w,
               const float* __restrict__ gates_b,
               const float* __restrict__ can_w,
               const float* __restrict__ can_b,
               float* __restrict__ out_f,
               float* __restrict__ out_att)
{
    extern __shared__ float sm[];
    float* f_s    = sm + OFF_F;
    float* h0_s   = sm + OFF_H0;
    float* h1_s   = sm + OFF_H1;
    float* wrel   = sm + OFF_WREL;   // {wf,wf,wh,wh} per (ci*9+k)*10+co, BN-folded
    float* wg2    = sm + OFF_WG2;    // {w1,w1,w2,w2} per co*10+ci, co in [0,20)
    float* wc2    = sm + OFF_WC2;    // {w1,w1,w2,w2} per co*10+ci, co in [0,10)
    float* attw2  = sm + OFF_ATTW2;
    float* gb_s   = sm + OFF_GB;
    float* cb_s   = sm + OFF_CB;
    float* b2_s   = sm + OFF_B2;
    float* attb_s = sm + OFF_ATTB;

    const int tid = threadIdx.x;
    const int b   = blockIdx.z;
    const int tx0 = blockIdx.x * TW;
    const int ty0 = blockIdx.y * TH;

    // ---- stage weights (folded + duplicated) ----
    for (int e = tid; e < C*9*C; e += NTHR) {
        int co = e % C;
        int k  = (e / C) % 9;
        int ci = e / (9*C);
        float inv = bn_gamma[co] * rsqrtf(bn_var[co] + 1e-5f);
        float wf = rel_w[(co*C2 + ci)*9 + k] * inv;
        float wh = rel_w[(co*C2 + C + ci)*9 + k] * inv;
        float* d = wrel + e*4;
        d[0] = wf; d[1] = wf; d[2] = wh; d[3] = wh;
    }
    for (int e = tid; e < C2*C; e += NTHR) {
        int co = e / C, ci = e % C;
        float w1 = gates_w[co*C2 + ci];
        float w2 = gates_w[co*C2 + C + ci];
        float* d = wg2 + e*4;
        d[0] = w1; d[1] = w1; d[2] = w2; d[3] = w2;
    }
    if (tid < C*C) {
        int co = tid / C, ci = tid % C;
        float w1 = can_w[co*C2 + ci];
        float w2 = can_w[co*C2 + C + ci];
        float* d = wc2 + tid*4;
        d[0] = w1; d[1] = w1; d[2] = w2; d[3] = w2;
    }
    if (tid < C2) {
        float aw = att_w[tid];
        attw2[tid*2] = aw; attw2[tid*2+1] = aw;
        gb_s[tid] = gates_b[tid];
    }
    if (tid < C) {
        cb_s[tid] = can_b[tid];
        float inv = bn_gamma[tid] * rsqrtf(bn_var[tid] + 1e-5f);
        b2_s[tid] = bn_beta[tid] - bn_mean[tid] * inv;
    }
    if (tid == 0) attb_s[0] = att_b[0];

    // ---- load haloed tiles: 10 slots/row (2 scalar edges + 8 aligned float2) ----
    if (tid < HALOH*10) {
        int ly = tid / 10, slot = tid - ly*10;
        int gy = ty0 - 1 + ly;
        bool okr = (gy >= 0) & (gy < HW);
        if (slot == 0 || slot == 9) {
            int lx = (slot == 0) ? 0 : 17;
            int gx = tx0 - 1 + lx;
            bool ok = okr & (gx >= 0) & (gx < HW);
            long gbase = ((long)(b*C)*HW + gy)*HW + gx;
            int  sbase = ly*PITCH + lx;
            #pragma unroll
            for (int ci = 0; ci < C; ++ci) {
                long gi = gbase + (long)ci*HW*HW;
                int  si = ci*HS + sbase;
                f_s [si] = ok ? f_node[gi] : 0.f;
                h0_s[si] = ok ? h0g[gi]    : 0.f;
                h1_s[si] = ok ? h1g[gi]    : 0.f;
            }
        } else {
            int lx = 2*slot - 1;             // 1,3,...,15
            int gx = tx0 - 1 + lx;           // even, in [0,126]
            long gbase = ((long)(b*C)*HW + gy)*HW + gx;
            int  sbase = ly*PITCH + lx;
            #pragma unroll
            for (int ci = 0; ci < C; ++ci) {
                long gi = gbase + (long)ci*HW*HW;
                int  si = ci*HS + sbase;
                float2 vf = okr ? *reinterpret_cast<const float2*>(f_node + gi) : make_float2(0.f,0.f);
                float2 v0 = okr ? *reinterpret_cast<const float2*>(h0g + gi)    : make_float2(0.f,0.f);
                float2 v1 = okr ? *reinterpret_cast<const float2*>(h1g + gi)    : make_float2(0.f,0.f);
                f_s [si] = vf.x; f_s [si+1] = vf.y;
                h0_s[si] = v0.x; h0_s[si+1] = v0.y;
                h1_s[si] = v1.x; h1_s[si+1] = v1.y;
            }
        }
    }
    __syncthreads();

    // ---- attention (2 px/iter, f32x2): scale h tiles in place ----
    if (tid < HS/2) {
        float ab = attb_s[0];
        int p2 = tid*2;
        ull v0[C], v1[C];
        ull s = pack2(ab, ab);
        #pragma unroll
        for (int ci = 0; ci < C; ++ci) {
            v0[ci] = *reinterpret_cast<ull*>(h0_s + ci*HS + p2);
            v1[ci] = *reinterpret_cast<ull*>(h1_s + ci*HS + p2);
            fma2(s, reinterpret_cast<ull*>(attw2)[ci],   v0[ci]);
            fma2(s, reinterpret_cast<ull*>(attw2)[C+ci], v1[ci]);
        }
        float s0, s1; unpack2(s, s0, s1);
        float a0 = fsigmoid(s0), a1 = fsigmoid(s1);
        ull ap = pack2(a0, a1);
        #pragma unroll
        for (int ci = 0; ci < C; ++ci) {
            *reinterpret_cast<ull*>(h0_s + ci*HS + p2) = mul2(v0[ci], ap);
            *reinterpret_cast<ull*>(h1_s + ci*HS + p2) = mul2(v1[ci], ap);
        }
        int ly0 = p2 / PITCH, lx0 = p2 - ly0*PITCH;
        if (ly0 >= 1 && ly0 <= TH && lx0 >= 1 && lx0 <= TW)
            out_att[((long)b*HW + (ty0 + ly0 - 1))*HW + (tx0 + lx0 - 1)] = a0;
        int p3 = p2 + 1;
        int ly1 = p3 / PITCH, lx1 = p3 - ly1*PITCH;
        if (ly1 >= 1 && ly1 <= TH && lx1 >= 1 && lx1 <= TW)
            out_att[((long)b*HW + (ty0 + ly1 - 1))*HW + (tx0 + lx1 - 1)] = a1;
    }
    __syncthreads();

    // ---- 3x3 conv: each half computes 5 output channels, 2 px (pixel-packed) ----
    const int half = tid >> 7;          // 0 or 1 -> co base half*5
    const int pp   = tid & 127;         // pixel-pair id
    const int txp  = (pp & 7) * 2;      // 0..14
    const int ty   = pp >> 3;           // 0..15
    const int base = ty*PITCH + txp;
    const int cob  = half*5;

    ull accf[5], acc0[5], acc1[5];
    #pragma unroll
    for (int j = 0; j < 5; ++j) {
        float bz = b2_s[cob + j];
        accf[j] = pack2(bz, bz);
        acc0[j] = 0ull; acc1[j] = 0ull;
    }

    for (int ci = 0; ci < C; ++ci) {
        const float* fb  = f_s  + ci*HS + base;
        const float* h0b = h0_s + ci*HS + base;
        const float* h1b = h1_s + ci*HS + base;
        const ulonglong2* wci = reinterpret_cast<const ulonglong2*>(wrel + ci*9*C*4) + cob;
        #pragma unroll
        for (int r = 0; r < 3; ++r) {
            const int ro = r*PITCH;
            float f0 = fb[ro],  f1 = fb[ro+1],  f2 = fb[ro+2],  f3 = fb[ro+3];
            float g0 = h0b[ro], g1 = h0b[ro+1], g2 = h0b[ro+2], g3 = h0b[ro+3];
            float e0 = h1b[ro], e1 = h1b[ro+1], e2 = h1b[ro+2], e3 = h1b[ro+3];
            ull fp[3] = { pack2(f0,f1), pack2(f1,f2), pack2(f2,f3) };
            ull p0[3] = { pack2(g0,g1), pack2(g1,g2), pack2(g2,g3) };
            ull p1[3] = { pack2(e0,e1), pack2(e1,e2), pack2(e2,e3) };
            #pragma unroll
            for (int kx = 0; kx < 3; ++kx) {
                const ulonglong2* wk = wci + (r*3 + kx)*C;
                ull fv = fp[kx], v0 = p0[kx], v1 = p1[kx];
                #pragma unroll
                for (int j = 0; j < 5; ++j) {
                    ulonglong2 w = wk[j];   // .x={wf,wf} .y={wh,wh}
                    fma2(accf[j], w.x, fv);
                    fma2(acc0[j], w.y, v0);
                    fma2(acc1[j], w.y, v1);
                }
            }
        }
    }

    // ---- comp_h for my 5 channels (ReLU+sum), exchange via smem ----
    __syncthreads();   // all conv reads of h1_s done before overwrite
    ull* ch_ex = reinterpret_cast<ull*>(h1_s);   // [co*128 + pp]
    #pragma unroll
    for (int j = 0; j < 5; ++j) {
        float af0, af1, x00, x01, x10, x11;
        unpack2(accf[j], af0, af1);
        unpack2(acc0[j], x00, x01);
        unpack2(acc1[j], x10, x11);
        float c0 = fmaxf(af0 + x00, 0.f) + fmaxf(af0 + x10, 0.f);
        float c1 = fmaxf(af1 + x01, 0.f) + fmaxf(af1 + x11, 0.f);
        ch_ex[(cob + j)*NPP + pp] = pack2(c0, c1);
    }
    __syncthreads();

    ull ch01[C], fc01[C];
    #pragma unroll
    for (int ci = 0; ci < C; ++ci) ch01[ci] = ch_ex[ci*NPP + pp];
    #pragma unroll
    for (int ci = 0; ci < C; ++ci) {
        const float* fc = f_s + ci*HS + (ty + 1)*PITCH + (txp + 1);
        fc01[ci] = pack2(fc[0], fc[1]);
    }

    // ---- gates: half 0 -> reset (writes r*f), half 1 -> update (writes u) ----
    __syncthreads();   // ch reads done before overwriting h1_s with rf_ex
    ull* rf_ex = reinterpret_cast<ull*>(h1_s);   // [ci*128 + pp]
    ull* u_ex  = reinterpret_cast<ull*>(h0_s);   // [co*128 + pp]
    {
        const int gcob = half * C;   // 0 -> reset block, 10 -> update block
        #pragma unroll
        for (int g = 0; g < C; ++g) {
            int co = gcob + g;
            float gb = gb_s[co];
            ull acc = pack2(gb, gb);
            const ulonglong2* w = reinterpret_cast<const ulonglong2*>(wg2) + co*C;
            #pragma unroll
            for (int ci = 0; ci < C; ++ci) {
                ulonglong2 ww = w[ci];
                fma2(acc, ww.x, ch01[ci]);
                fma2(acc, ww.y, fc01[ci]);
            }
            float a0, a1; unpack2(acc, a0, a1);
            ull s = pack2(fsigmoid(a0), fsigmoid(a1));
            if (half == 0) rf_ex[g*NPP + pp] = mul2(s, fc01[g]);
            else           u_ex [g*NPP + pp] = s;
        }
    }
    __syncthreads();

    // ---- candidate + update for my 5 channels, write output ----
    ull rf01[C];
    #pragma unroll
    for (int ci = 0; ci < C; ++ci) rf01[ci] = rf_ex[ci*NPP + pp];

    const int gy = ty0 + ty, gx = tx0 + txp;
    #pragma unroll
    for (int j = 0; j < 5; ++j) {
        int co = cob + j;
        float cb = cb_s[co];
        ull g = pack2(cb, cb);
        const ulonglong2* w = reinterpret_cast<const ulonglong2*>(wc2) + co*C;
        #pragma unroll
        for (int ci = 0; ci < C; ++ci) {
            ulonglong2 ww = w[ci];
            fma2(g, ww.x, ch01[ci]);
            fma2(g, ww.y, rf01[ci]);
        }
        float gg0, gg1; unpack2(g, gg0, gg1);
        float t0 = ftanh_fast(gg0), t1 = ftanh_fast(gg1);
        float fc0, fc1; unpack2(fc01[co], fc0, fc1);
        float u0, u1;  unpack2(u_ex[co*NPP + pp], u0, u1);
        float r0 = fc0 + u0*(t0 - fc0);
        float r1 = fc1 + u1*(t1 - fc1);
        long o = ((long)(b*C + co)*HW + gy)*HW + gx;
        *reinterpret_cast<float2*>(out_f + o) = make_float2(r0, r1);
    }
}

extern "C" void kernel_launch(void* const* d_in, const int* in_sizes, int n_in,
                              void* d_out, int out_size) {
    (void)n_in; (void)out_size;
    const float* f_node   = (const float*)d_in[0];
    const float* h0       = (const float*)d_in[1];
    const float* h1       = (const float*)d_in[2];
    // d_in[3] = p_nodes (unused), d_in[4] = xf (unused)
    const float* att_w    = (const float*)d_in[5];
    const float* att_b    = (const float*)d_in[6];
    const float* rel_w    = (const float*)d_in[7];
    const float* bn_gamma = (const float*)d_in[8];
    const float* bn_beta  = (const float*)d_in[9];
    const float* bn_mean  = (const float*)d_in[10];
    const float* bn_var   = (const float*)d_in[11];
    const float* gates_w  = (const float*)d_in[12];
    const float* gates_b  = (const float*)d_in[13];
    const float* can_w    = (const float*)d_in[14];
    const float* can_b    = (const float*)d_in[15];

    int B = in_sizes[0] / (C * HW * HW);
    float* out_f   = (float*)d_out;
    float* out_att = out_f + (long)B * C * HW * HW;

    static bool attr_set = false;
    if (!attr_set) {
        cudaFuncSetAttribute(fused_tree_gru,
                             cudaFuncAttributeMaxDynamicSharedMemorySize, SMEM_BYTES);
        attr_set = true;
    }

    dim3 grid(HW / TW, HW / TH, B);
    fused_tree_gru<<<grid, NTHR, SMEM_BYTES>>>(f_node, h0, h1, att_w, att_b, rel_w,
                                               bn_gamma, bn_beta, bn_mean, bn_var,
                                               gates_w, gates_b, can_w, can_b,
                                               out_f, out_att);
}

// round 9
// speedup vs baseline: 1.2332x; 1.2332x over previous
#include <cuda_runtime.h>

#define C     10
#define C2    20
#define HW    128
#define TW    16
#define TH    16
#define PITCH 19            // odd pitch -> conflict-free
#define HALOH 18
#define HS    (PITCH*HALOH) // 342
#define NTHR  256

typedef unsigned long long ull;

// shared layout (floats)
#define OFF_F     0
#define OFF_H0    (C*HS)                    // 3420
#define OFF_H1    (2*C*HS)                  // 6840
#define OFF_WREL  (3*C*HS)                  // 10260 (x4B = 41040, 16B aligned)
// wrel: (ci*9+k)*5+cp -> {wf(2cp), wf(2cp+1), wh(2cp), wh(2cp+1)}  450 entries
#define OFF_WG2   (OFF_WREL + 450*4)        // 12060  float2 {w1,w2} per co*10+ci, co<20
#define OFF_WC2   (OFF_WG2 + 200*2)         // 12460  float2 {w1,w2} per co*10+ci, co<10
#define OFF_ATTW2 (OFF_WC2 + 100*2)         // 12660  {w,w} dup per ci<20
#define OFF_GB    (OFF_ATTW2 + C2*2)        // 12700
#define OFF_CB    (OFF_GB + C2)             // 12720
#define OFF_B2    (OFF_CB + C)              // 12730
#define OFF_ATTB  (OFF_B2 + C)              // 12740
#define SMEM_FLOATS (OFF_ATTB + 1)
#define SMEM_BYTES (SMEM_FLOATS*4)          // ~51 KB -> 3+ CTAs/SM

__device__ __forceinline__ float fsigmoid(float x) { return 1.0f / (1.0f + __expf(-x)); }
__device__ __forceinline__ float ftanh_fast(float x) { return 1.0f - 2.0f / (__expf(2.0f * x) + 1.0f); }

__device__ __forceinline__ ull pack2(float lo, float hi) {
    ull r; asm("mov.b64 %0, {%1,%2};" : "=l"(r) : "f"(lo), "f"(hi)); return r;
}
__device__ __forceinline__ void unpack2(ull v, float& lo, float& hi) {
    asm("mov.b64 {%0,%1}, %2;" : "=f"(lo), "=f"(hi) : "l"(v));
}
__device__ __forceinline__ void fma2(ull& acc, ull a, ull b) {
    asm("fma.rn.f32x2 %0, %1, %2, %0;" : "+l"(acc) : "l"(a), "l"(b));
}
__device__ __forceinline__ ull mul2(ull a, ull b) {
    ull r; asm("mul.rn.f32x2 %0, %1, %2;" : "=l"(r) : "l"(a), "l"(b)); return r;
}

__global__ void __launch_bounds__(NTHR, 3)
fused_tree_gru(const float* __restrict__ f_node,
               const float* __restrict__ h0g,
               const float* __restrict__ h1g,
               const float* __restrict__ att_w,
               const float* __restrict__ att_b,
               const float* __restrict__ rel_w,
               const float* __restrict__ bn_gamma,
               const float* __restrict__ bn_beta,
               const float* __restrict__ bn_mean,
               const float* __restrict__ bn_var,
               const float* __restrict__ gates_w,
               const float* __restrict__ gates_b,
               const float* __restrict__ can_w,
               const float* __restrict__ can_b,
               float* __restrict__ out_f,
               float* __restrict__ out_att)
{
    extern __shared__ float sm[];
    float*  f_s    = sm + OFF_F;
    float*  h0_s   = sm + OFF_H0;
    float*  h1_s   = sm + OFF_H1;
    float*  wrel   = sm + OFF_WREL;
    float2* wg2    = reinterpret_cast<float2*>(sm + OFF_WG2);
    float2* wc2    = reinterpret_cast<float2*>(sm + OFF_WC2);
    float*  attw2  = sm + OFF_ATTW2;
    float*  gb_s   = sm + OFF_GB;
    float*  cb_s   = sm + OFF_CB;
    float*  b2_s   = sm + OFF_B2;
    float*  attb_s = sm + OFF_ATTB;

    const int tid = threadIdx.x;
    const int b   = blockIdx.z;
    const int tx0 = blockIdx.x * TW;
    const int ty0 = blockIdx.y * TH;

    // ---- stage conv weights (BN-folded, co-pair packed) ----
    for (int e = tid; e < C*9*5; e += NTHR) {
        int cp = e % 5;
        int k  = (e / 5) % 9;
        int ci = e / 45;
        int coA = 2*cp, coB = 2*cp + 1;
        float invA = bn_gamma[coA] * rsqrtf(bn_var[coA] + 1e-5f);
        float invB = bn_gamma[coB] * rsqrtf(bn_var[coB] + 1e-5f);
        float* d = wrel + e*4;
        d[0] = rel_w[(coA*C2 + ci)*9 + k] * invA;
        d[1] = rel_w[(coB*C2 + ci)*9 + k] * invB;
        d[2] = rel_w[(coA*C2 + C + ci)*9 + k] * invA;
        d[3] = rel_w[(coB*C2 + C + ci)*9 + k] * invB;
    }
    if (tid < C2*C) {
        int co = tid / C, ci = tid % C;
        wg2[tid] = make_float2(gates_w[co*C2 + ci], gates_w[co*C2 + C + ci]);
    }
    if (tid < C*C) {
        int co = tid / C, ci = tid % C;
        wc2[tid] = make_float2(can_w[co*C2 + ci], can_w[co*C2 + C + ci]);
    }
    if (tid < C2) {
        float aw = att_w[tid];
        attw2[tid*2] = aw; attw2[tid*2+1] = aw;
        gb_s[tid] = gates_b[tid];
    }
    if (tid < C) {
        cb_s[tid] = can_b[tid];
        float inv = bn_gamma[tid] * rsqrtf(bn_var[tid] + 1e-5f);
        b2_s[tid] = bn_beta[tid] - bn_mean[tid] * inv;
    }
    if (tid == 0) attb_s[0] = att_b[0];

    // ---- load haloed tiles: 10 slots/row (2 scalar edges + 8 aligned float2) ----
    if (tid < HALOH*10) {
        int ly = tid / 10, slot = tid - ly*10;
        int gy = ty0 - 1 + ly;
        bool okr = (gy >= 0) & (gy < HW);
        if (slot == 0 || slot == 9) {
            int lx = (slot == 0) ? 0 : 17;
            int gx = tx0 - 1 + lx;
            bool ok = okr & (gx >= 0) & (gx < HW);
            long gbase = ((long)(b*C)*HW + gy)*HW + gx;
            int  sbase = ly*PITCH + lx;
            #pragma unroll
            for (int ci = 0; ci < C; ++ci) {
                long gi = gbase + (long)ci*HW*HW;
                int  si = ci*HS + sbase;
                f_s [si] = ok ? f_node[gi] : 0.f;
                h0_s[si] = ok ? h0g[gi]    : 0.f;
                h1_s[si] = ok ? h1g[gi]    : 0.f;
            }
        } else {
            int lx = 2*slot - 1;             // 1,3,...,15
            int gx = tx0 - 1 + lx;           // even, in [0,126]
            long gbase = ((long)(b*C)*HW + gy)*HW + gx;
            int  sbase = ly*PITCH + lx;
            #pragma unroll
            for (int ci = 0; ci < C; ++ci) {
                long gi = gbase + (long)ci*HW*HW;
                int  si = ci*HS + sbase;
                float2 vf = okr ? *reinterpret_cast<const float2*>(f_node + gi) : make_float2(0.f,0.f);
                float2 v0 = okr ? *reinterpret_cast<const float2*>(h0g + gi)    : make_float2(0.f,0.f);
                float2 v1 = okr ? *reinterpret_cast<const float2*>(h1g + gi)    : make_float2(0.f,0.f);
                f_s [si] = vf.x; f_s [si+1] = vf.y;
                h0_s[si] = v0.x; h0_s[si+1] = v0.y;
                h1_s[si] = v1.x; h1_s[si+1] = v1.y;
            }
        }
    }
    __syncthreads();

    // ---- attention (2 px/iter, f32x2): scale h tiles in place ----
    if (tid < HS/2) {
        float ab = attb_s[0];
        int p2 = tid*2;
        ull v0[C], v1[C];
        ull s = pack2(ab, ab);
        #pragma unroll
        for (int ci = 0; ci < C; ++ci) {
            v0[ci] = *reinterpret_cast<ull*>(h0_s + ci*HS + p2);
            v1[ci] = *reinterpret_cast<ull*>(h1_s + ci*HS + p2);
            fma2(s, reinterpret_cast<ull*>(attw2)[ci],   v0[ci]);
            fma2(s, reinterpret_cast<ull*>(attw2)[C+ci], v1[ci]);
        }
        float s0, s1; unpack2(s, s0, s1);
        float a0 = fsigmoid(s0), a1 = fsigmoid(s1);
        ull ap = pack2(a0, a1);
        #pragma unroll
        for (int ci = 0; ci < C; ++ci) {
            *reinterpret_cast<ull*>(h0_s + ci*HS + p2) = mul2(v0[ci], ap);
            *reinterpret_cast<ull*>(h1_s + ci*HS + p2) = mul2(v1[ci], ap);
        }
        int ly0 = p2 / PITCH, lx0 = p2 - ly0*PITCH;
        if (ly0 >= 1 && ly0 <= TH && lx0 >= 1 && lx0 <= TW)
            out_att[((long)b*HW + (ty0 + ly0 - 1))*HW + (tx0 + lx0 - 1)] = a0;
        int p3 = p2 + 1;
        int ly1 = p3 / PITCH, lx1 = p3 - ly1*PITCH;
        if (ly1 >= 1 && ly1 <= TH && lx1 >= 1 && lx1 <= TW)
            out_att[((long)b*HW + (ty0 + ly1 - 1))*HW + (tx0 + lx1 - 1)] = a1;
    }
    __syncthreads();

    // ---- 3x3 conv: 1 px/thread, co-pairs packed in f32x2 (15 ull accs) ----
    const int tx   = tid & 15;
    const int ty   = tid >> 4;
    const int base = ty*PITCH + tx;

    ull accf[5], acc0[5], acc1[5];
    #pragma unroll
    for (int cp = 0; cp < 5; ++cp) {
        accf[cp] = pack2(b2_s[2*cp], b2_s[2*cp+1]);
        acc0[cp] = 0ull; acc1[cp] = 0ull;
    }

    for (int ci = 0; ci < C; ++ci) {
        const float* fb  = f_s  + ci*HS + base;
        const float* h0b = h0_s + ci*HS + base;
        const float* h1b = h1_s + ci*HS + base;
        const ulonglong2* wci = reinterpret_cast<const ulonglong2*>(wrel) + ci*45;
        #pragma unroll
        for (int r = 0; r < 3; ++r) {
            const int ro = r*PITCH;
            ull fd[3], gd[3], ed[3];
            #pragma unroll
            for (int t = 0; t < 3; ++t) {
                float fv = fb[ro+t], gv = h0b[ro+t], ev = h1b[ro+t];
                fd[t] = pack2(fv, fv);
                gd[t] = pack2(gv, gv);
                ed[t] = pack2(ev, ev);
            }
            #pragma unroll
            for (int kx = 0; kx < 3; ++kx) {
                const ulonglong2* wk = wci + (r*3 + kx)*5;
                #pragma unroll
                for (int cp = 0; cp < 5; ++cp) {
                    ulonglong2 w = wk[cp];   // .x={wfA,wfB} .y={whA,whB}
                    fma2(accf[cp], w.x, fd[kx]);
                    fma2(acc0[cp], w.y, gd[kx]);
                    fma2(acc1[cp], w.y, ed[kx]);
                }
            }
        }
    }

    // ---- epilogue: ReLU + sum (scalar, 1 px) ----
    float ch[C], fc[C];
    #pragma unroll
    for (int cp = 0; cp < 5; ++cp) {
        float fA, fB, aA, aB, bA, bB;
        unpack2(accf[cp], fA, fB);
        unpack2(acc0[cp], aA, aB);
        unpack2(acc1[cp], bA, bB);
        ch[2*cp]   = fmaxf(fA + aA, 0.f) + fmaxf(fA + bA, 0.f);
        ch[2*cp+1] = fmaxf(fB + aB, 0.f) + fmaxf(fB + bB, 0.f);
    }
    #pragma unroll
    for (int ci = 0; ci < C; ++ci)
        fc[ci] = f_s[ci*HS + (ty + 1)*PITCH + (tx + 1)];

    // ---- ConvGRU gates (1x1), scalar, float2 weights from SMEM ----
    float rr[C], uu[C];
    #pragma unroll
    for (int co = 0; co < C2; ++co) {
        float g = gb_s[co];
        const float2* w = wg2 + co*C;
        #pragma unroll
        for (int ci = 0; ci < C; ++ci) {
            float2 ww = w[ci];
            g += ww.x*ch[ci] + ww.y*fc[ci];
        }
        float s = fsigmoid(g);
        if (co < C) rr[co] = s; else uu[co - C] = s;
    }
    float rf[C];
    #pragma unroll
    for (int ci = 0; ci < C; ++ci) rf[ci] = rr[ci]*fc[ci];

    // ---- candidate + update, write output ----
    const int gy = ty0 + ty, gx = tx0 + tx;
    #pragma unroll
    for (int co = 0; co < C; ++co) {
        float g = cb_s[co];
        const float2* w = wc2 + co*C;
        #pragma unroll
        for (int ci = 0; ci < C; ++ci) {
            float2 ww = w[ci];
            g += ww.x*ch[ci] + ww.y*rf[ci];
        }
        float t = ftanh_fast(g);
        float res = fc[co] + uu[co]*(t - fc[co]);
        out_f[((long)(b*C + co)*HW + gy)*HW + gx] = res;
    }
}

extern "C" void kernel_launch(void* const* d_in, const int* in_sizes, int n_in,
                              void* d_out, int out_size) {
    (void)n_in; (void)out_size;
    const float* f_node   = (const float*)d_in[0];
    const float* h0       = (const float*)d_in[1];
    const float* h1       = (const float*)d_in[2];
    // d_in[3] = p_nodes (unused), d_in[4] = xf (unused)
    const float* att_w    = (const float*)d_in[5];
    const float* att_b    = (const float*)d_in[6];
    const float* rel_w    = (const float*)d_in[7];
    const float* bn_gamma = (const float*)d_in[8];
    const float* bn_beta  = (const float*)d_in[9];
    const float* bn_mean  = (const float*)d_in[10];
    const float* bn_var   = (const float*)d_in[11];
    const float* gates_w  = (const float*)d_in[12];
    const float* gates_b  = (const float*)d_in[13];
    const float* can_w    = (const float*)d_in[14];
    const float* can_b    = (const float*)d_in[15];

    int B = in_sizes[0] / (C * HW * HW);
    float* out_f   = (float*)d_out;
    float* out_att = out_f + (long)B * C * HW * HW;

    static bool attr_set = false;
    if (!attr_set) {
        cudaFuncSetAttribute(fused_tree_gru,
                             cudaFuncAttributeMaxDynamicSharedMemorySize, SMEM_BYTES);
        attr_set = true;
    }

    dim3 grid(HW / TW, HW / TH, B);
    fused_tree_gru<<<grid, NTHR, SMEM_BYTES>>>(f_node, h0, h1, att_w, att_b, rel_w,
                                               bn_gamma, bn_beta, bn_mean, bn_var,
                                               gates_w, gates_b, can_w, can_b,
                                               out_f, out_att);
}

// round 10
// speedup vs baseline: 1.6237x; 1.3167x over previous
#include <cuda_runtime.h>

#define C     10
#define C2    20
#define HW    128
#define TW    32
#define TH    16
#define PITCH 35            // odd pitch -> conflict-free half-warp offsets
#define HALOH 18
#define HS    (PITCH*HALOH) // 630
#define NTHR  256

typedef unsigned long long ull;

// shared layout (floats)
#define OFF_F     0
#define OFF_H0    (C*HS)                    // 6300
#define OFF_H1    (2*C*HS)                  // 12600
#define OFF_WREL  (3*C*HS)                  // 18900 (x4B = 75600, 16B aligned)
#define OFF_WG2   (OFF_WREL + 450*4)        // 20700
#define OFF_WC2   (OFF_WG2 + 200*4)         // 21500
#define OFF_GB    (OFF_WC2 + 100*4)         // 21900
#define OFF_CB    (OFF_GB + C2)             // 21920
#define OFF_B2    (OFF_CB + C)              // 21930
#define SMEM_FLOATS (OFF_B2 + C)            // 21940
#define SMEM_BYTES (SMEM_FLOATS*4)          // ~87.8 KB

__device__ __forceinline__ float fsigmoid(float x) { return 1.0f / (1.0f + __expf(-x)); }
__device__ __forceinline__ float ftanh_fast(float x) { return 1.0f - 2.0f / (__expf(2.0f * x) + 1.0f); }

__device__ __forceinline__ ull pack2(float lo, float hi) {
    ull r; asm("mov.b64 %0, {%1,%2};" : "=l"(r) : "f"(lo), "f"(hi)); return r;
}
__device__ __forceinline__ void unpack2(ull v, float& lo, float& hi) {
    asm("mov.b64 {%0,%1}, %2;" : "=f"(lo), "=f"(hi) : "l"(v));
}
__device__ __forceinline__ void fma2(ull& acc, ull a, ull b) {
    asm("fma.rn.f32x2 %0, %1, %2, %0;" : "+l"(acc) : "l"(a), "l"(b));
}
__device__ __forceinline__ ull mul2(ull a, ull b) {
    ull r; asm("mul.rn.f32x2 %0, %1, %2;" : "=l"(r) : "l"(a), "l"(b)); return r;
}

__global__ void __launch_bounds__(NTHR, 2)
fused_tree_gru(const float* __restrict__ f_node,
               const float* __restrict__ h0g,
               const float* __restrict__ h1g,
               const float* __restrict__ att_w,
               const float* __restrict__ att_b,
               const float* __restrict__ rel_w,
               const float* __restrict__ bn_gamma,
               const float* __restrict__ bn_beta,
               const float* __restrict__ bn_mean,
               const float* __restrict__ bn_var,
               const float* __restrict__ gates_w,
               const float* __restrict__ gates_b,
               const float* __restrict__ can_w,
               const float* __restrict__ can_b,
               float* __restrict__ out_f,
               float* __restrict__ out_att)
{
    extern __shared__ float sm[];
    float* f_s   = sm + OFF_F;
    float* h0_s  = sm + OFF_H0;
    float* h1_s  = sm + OFF_H1;
    float* wrel  = sm + OFF_WREL;   // (ci*9+k)*5+cp -> {wfA,wfB,whA,whB} BN-folded
    float* wg2   = sm + OFF_WG2;    // {w1,w1,w2,w2} per co*10+ci, co in [0,20)
    float* wc2   = sm + OFF_WC2;    // {w1,w1,w2,w2} per co*10+ci, co in [0,10)
    float* gb_s  = sm + OFF_GB;
    float* cb_s  = sm + OFF_CB;
    float* b2_s  = sm + OFF_B2;

    const int tid = threadIdx.x;
    const int b   = blockIdx.z;
    const int tx0 = blockIdx.x * TW;
    const int ty0 = blockIdx.y * TH;

    // ---- stage weights (folded, co-pair packed) ----
    for (int e = tid; e < C*9*5; e += NTHR) {
        int cp = e % 5;
        int k  = (e / 5) % 9;
        int ci = e / 45;
        int coA = 2*cp, coB = 2*cp + 1;
        float invA = bn_gamma[coA] * rsqrtf(bn_var[coA] + 1e-5f);
        float invB = bn_gamma[coB] * rsqrtf(bn_var[coB] + 1e-5f);
        float* d = wrel + e*4;
        d[0] = rel_w[(coA*C2 + ci)*9 + k] * invA;
        d[1] = rel_w[(coB*C2 + ci)*9 + k] * invB;
        d[2] = rel_w[(coA*C2 + C + ci)*9 + k] * invA;
        d[3] = rel_w[(coB*C2 + C + ci)*9 + k] * invB;
    }
    for (int e = tid; e < C2*C; e += NTHR) {
        int co = e / C, ci = e % C;
        float w1 = gates_w[co*C2 + ci];
        float w2 = gates_w[co*C2 + C + ci];
        float* d = wg2 + e*4;
        d[0] = w1; d[1] = w1; d[2] = w2; d[3] = w2;
    }
    if (tid < C*C) {
        int co = tid / C, ci = tid % C;
        float w1 = can_w[co*C2 + ci];
        float w2 = can_w[co*C2 + C + ci];
        float* d = wc2 + tid*4;
        d[0] = w1; d[1] = w1; d[2] = w2; d[3] = w2;
    }
    if (tid < C2) gb_s[tid] = gates_b[tid];
    if (tid < C) {
        cb_s[tid] = can_b[tid];
        float inv = bn_gamma[tid] * rsqrtf(bn_var[tid] + 1e-5f);
        b2_s[tid] = bn_beta[tid] - bn_mean[tid] * inv;
    }

    // ---- fused prologue: load halo tiles + inline attention scaling ----
    {
        const float ab = __ldg(att_b);
        for (int i = tid; i < 18*18; i += NTHR) {
            int ly = i / 18, slot = i - ly*18;
            int gy = ty0 - 1 + ly;
            bool okr = (gy >= 0) & (gy < HW);
            if (slot == 0 || slot == 17) {
                // edge columns: scalar path
                int lx = (slot == 0) ? 0 : 33;
                int gx = tx0 - 1 + lx;
                bool ok = okr & (gx >= 0) & (gx < HW);
                long gbase = ((long)(b*C)*HW + gy)*HW + gx;
                int  sbase = ly*PITCH + lx;
                float v0[C], v1[C];
                float s = ab;
                #pragma unroll
                for (int ci = 0; ci < C; ++ci) {
                    long gi = gbase + (long)ci*HW*HW;
                    f_s[ci*HS + sbase] = ok ? f_node[gi] : 0.f;
                    v0[ci] = ok ? h0g[gi] : 0.f;
                    v1[ci] = ok ? h1g[gi] : 0.f;
                    s += __ldg(att_w + ci)*v0[ci] + __ldg(att_w + C + ci)*v1[ci];
                }
                float a = fsigmoid(s);
                #pragma unroll
                for (int ci = 0; ci < C; ++ci) {
                    h0_s[ci*HS + sbase] = v0[ci]*a;
                    h1_s[ci*HS + sbase] = v1[ci]*a;
                }
            } else {
                // interior: aligned float2 path, 2 pixels
                int lx = 2*slot - 1;             // 1,3,...,31
                int gx = tx0 - 1 + lx;           // even, in [0,126]
                long gbase = ((long)(b*C)*HW + gy)*HW + gx;
                int  sbase = ly*PITCH + lx;
                float2 v0[C], v1[C];
                float s0 = ab, s1 = ab;
                #pragma unroll
                for (int ci = 0; ci < C; ++ci) {
                    long gi = gbase + (long)ci*HW*HW;
                    float2 vf = okr ? *reinterpret_cast<const float2*>(f_node + gi) : make_float2(0.f,0.f);
                    v0[ci]    = okr ? *reinterpret_cast<const float2*>(h0g + gi)    : make_float2(0.f,0.f);
                    v1[ci]    = okr ? *reinterpret_cast<const float2*>(h1g + gi)    : make_float2(0.f,0.f);
                    int si = ci*HS + sbase;
                    f_s[si] = vf.x; f_s[si+1] = vf.y;
                    float aw0 = __ldg(att_w + ci), aw1 = __ldg(att_w + C + ci);
                    s0 += aw0*v0[ci].x + aw1*v1[ci].x;
                    s1 += aw0*v0[ci].y + aw1*v1[ci].y;
                }
                float a0 = fsigmoid(s0), a1 = fsigmoid(s1);
                #pragma unroll
                for (int ci = 0; ci < C; ++ci) {
                    int si = ci*HS + sbase;
                    h0_s[si] = v0[ci].x*a0; h0_s[si+1] = v0[ci].y*a1;
                    h1_s[si] = v1[ci].x*a0; h1_s[si+1] = v1[ci].y*a1;
                }
                if (ly >= 1 && ly <= TH) {
                    long ao = ((long)b*HW + gy)*HW + gx;   // gx = tx0+lx-1, even
                    *reinterpret_cast<float2*>(out_att + ao) = make_float2(a0, a1);
                }
            }
        }
    }
    __syncthreads();

    // ---- 3x3 conv: acc [co-pair][px], bias pre-folded into accf ----
    const int txp  = (tid & 15) * 2;
    const int ty   = tid >> 4;
    const int base = ty*PITCH + txp;

    ull accf[5][2], acc0[5][2], acc1[5][2];
    #pragma unroll
    for (int cp = 0; cp < 5; ++cp) {
        ull bz = pack2(b2_s[2*cp], b2_s[2*cp+1]);
        accf[cp][0] = bz; accf[cp][1] = bz;
        acc0[cp][0] = acc0[cp][1] = 0ull;
        acc1[cp][0] = acc1[cp][1] = 0ull;
    }

    for (int ci = 0; ci < C; ++ci) {
        const float* fb  = f_s  + ci*HS + base;
        const float* h0b = h0_s + ci*HS + base;
        const float* h1b = h1_s + ci*HS + base;
        const ulonglong2* wci = reinterpret_cast<const ulonglong2*>(wrel) + ci*45;
        #pragma unroll
        for (int r = 0; r < 3; ++r) {
            const int ro = r*PITCH;
            ull fd[4], gd[4], ed[4];
            #pragma unroll
            for (int t = 0; t < 4; ++t) {
                float fv = fb[ro+t], gv = h0b[ro+t], ev = h1b[ro+t];
                fd[t] = pack2(fv, fv);
                gd[t] = pack2(gv, gv);
                ed[t] = pack2(ev, ev);
            }
            #pragma unroll
            for (int kx = 0; kx < 3; ++kx) {
                const ulonglong2* wk = wci + (r*3 + kx)*5;
                #pragma unroll
                for (int cp = 0; cp < 5; ++cp) {
                    ulonglong2 w = wk[cp];   // .x={wfA,wfB} .y={whA,whB}
                    fma2(accf[cp][0], w.x, fd[kx]);
                    fma2(accf[cp][1], w.x, fd[kx+1]);
                    fma2(acc0[cp][0], w.y, gd[kx]);
                    fma2(acc0[cp][1], w.y, gd[kx+1]);
                    fma2(acc1[cp][0], w.y, ed[kx]);
                    fma2(acc1[cp][1], w.y, ed[kx+1]);
                }
            }
        }
    }

    // ---- epilogue: ReLU + sum -> packed comp_h / f center ----
    ull ch01[C], fc01[C];
    #pragma unroll
    for (int cp = 0; cp < 5; ++cp) {
        float chv[2][2];
        #pragma unroll
        for (int px = 0; px < 2; ++px) {
            float afA, afB, x0A, x0B, x1A, x1B;
            unpack2(accf[cp][px], afA, afB);
            unpack2(acc0[cp][px], x0A, x0B);
            unpack2(acc1[cp][px], x1A, x1B);
            chv[px][0] = fmaxf(afA + x0A, 0.f) + fmaxf(afA + x1A, 0.f);
            chv[px][1] = fmaxf(afB + x0B, 0.f) + fmaxf(afB + x1B, 0.f);
        }
        ch01[2*cp]   = pack2(chv[0][0], chv[1][0]);
        ch01[2*cp+1] = pack2(chv[0][1], chv[1][1]);
    }
    #pragma unroll
    for (int ci = 0; ci < C; ++ci) {
        const float* fc = f_s + ci*HS + (ty + 1)*PITCH + (txp + 1);
        fc01[ci] = pack2(fc[0], fc[1]);
    }

    // ---- ConvGRU gates (1x1), packed f32x2 ----
    ull r01[C], u01[C];
    #pragma unroll
    for (int co = 0; co < C2; ++co) {
        float gb = gb_s[co];
        ull g = pack2(gb, gb);
        const ulonglong2* w = reinterpret_cast<const ulonglong2*>(wg2) + co*C;
        #pragma unroll
        for (int ci = 0; ci < C; ++ci) {
            ulonglong2 ww = w[ci];
            fma2(g, ww.x, ch01[ci]);
            fma2(g, ww.y, fc01[ci]);
        }
        float gg0, gg1; unpack2(g, gg0, gg1);
        ull s = pack2(fsigmoid(gg0), fsigmoid(gg1));
        if (co < C) r01[co] = s; else u01[co - C] = s;
    }
    ull rf01[C];
    #pragma unroll
    for (int ci = 0; ci < C; ++ci) rf01[ci] = mul2(r01[ci], fc01[ci]);

    // ---- candidate + update, write output ----
    const int gy = ty0 + ty, gx = tx0 + txp;
    #pragma unroll
    for (int co = 0; co < C; ++co) {
        float cb = cb_s[co];
        ull g = pack2(cb, cb);
        const ulonglong2* w = reinterpret_cast<const ulonglong2*>(wc2) + co*C;
        #pragma unroll
        for (int ci = 0; ci < C; ++ci) {
            ulonglong2 ww = w[ci];
            fma2(g, ww.x, ch01[ci]);
            fma2(g, ww.y, rf01[ci]);
        }
        float gg0, gg1; unpack2(g, gg0, gg1);
        float t0 = ftanh_fast(gg0), t1 = ftanh_fast(gg1);
        float fc0, fc1; unpack2(fc01[co], fc0, fc1);
        float u0, u1;  unpack2(u01[co], u0, u1);
        float r0 = fc0 + u0*(t0 - fc0);
        float r1 = fc1 + u1*(t1 - fc1);
        long o = ((long)(b*C + co)*HW + gy)*HW + gx;
        *reinterpret_cast<float2*>(out_f + o) = make_float2(r0, r1);
    }
}

extern "C" void kernel_launch(void* const* d_in, const int* in_sizes, int n_in,
                              void* d_out, int out_size) {
    (void)n_in; (void)out_size;
    const float* f_node   = (const float*)d_in[0];
    const float* h0       = (const float*)d_in[1];
    const float* h1       = (const float*)d_in[2];
    // d_in[3] = p_nodes (unused), d_in[4] = xf (unused)
    const float* att_w    = (const float*)d_in[5];
    const float* att_b    = (const float*)d_in[6];
    const float* rel_w    = (const float*)d_in[7];
    const float* bn_gamma = (const float*)d_in[8];
    const float* bn_beta  = (const float*)d_in[9];
    const float* bn_mean  = (const float*)d_in[10];
    const float* bn_var   = (const float*)d_in[11];
    const float* gates_w  = (const float*)d_in[12];
    const float* gates_b  = (const float*)d_in[13];
    const float* can_w    = (const float*)d_in[14];
    const float* can_b    = (const float*)d_in[15];

    int B = in_sizes[0] / (C * HW * HW);
    float* out_f   = (float*)d_out;
    float* out_att = out_f + (long)B * C * HW * HW;

    static bool attr_set = false;
    if (!attr_set) {
        cudaFuncSetAttribute(fused_tree_gru,
                             cudaFuncAttributeMaxDynamicSharedMemorySize, SMEM_BYTES);
        attr_set = true;
    }

    dim3 grid(HW / TW, HW / TH, B);
    fused_tree_gru<<<grid, NTHR, SMEM_BYTES>>>(f_node, h0, h1, att_w, att_b, rel_w,
                                               bn_gamma, bn_beta, bn_mean, bn_var,
                                               gates_w, gates_b, can_w, can_b,
                                               out_f, out_att);
}